// round 2
// baseline (speedup 1.0000x reference)
#include <cuda_runtime.h>
#include <cuda_bf16.h>
#include <cstdint>

// Problem constants
#define BATCH   4
#define SEQ     2048
#define DMODEL  1024
#define HEADS   16
#define DHEAD   64
#define EDIM    1024          // HEADS*DHEAD
#define SCALE   0.125f        // 1/sqrt(64)

// Scratch (device globals; allocation in kernel_launch is forbidden)
__device__ float g_Q[(size_t)BATCH * HEADS * SEQ * DHEAD];  // [b,h,t,d]
__device__ float g_K[(size_t)BATCH * HEADS * SEQ * DHEAD];  // [b,h,t,d]
__device__ float g_V[(size_t)BATCH * HEADS * SEQ * DHEAD];  // [b,h,t,d]
__device__ float g_O[(size_t)BATCH * SEQ * EDIM];           // [b,t,(h d)]

// ---------------------------------------------------------------------------
// TN SGEMM: C[m,n] = sum_k A[m,k] * B[n,k]   (both row-major, K contiguous)
// 128x128 tile, BK=16, 256 threads, 8x8 per-thread microtile.
// MODE 0: A=q,  B=Wq,  epilogue scatters n=(d*16+h) -> g_Q[b,h,t,d]
// MODE 1: A=kv, B=Wkv, epilogue scatters n=(d*32+kk*16+h) -> g_K/g_V[b,h,t,d]
// MODE 2: A=g_O, B=W0, epilogue writes C[m*N+n] (d_out)
// ---------------------------------------------------------------------------
template <int MODE>
__global__ __launch_bounds__(256) void gemm_tn(const float* __restrict__ A,
                                               const float* __restrict__ Bw,
                                               float* __restrict__ C,
                                               int M, int N, int K) {
    __shared__ float As[16][132];
    __shared__ float Bs[16][132];

    const int tid = threadIdx.x;
    const int ty = tid >> 4;          // 0..15
    const int tx = tid & 15;          // 0..15
    const int m0 = blockIdx.y * 128;
    const int n0 = blockIdx.x * 128;

    const float* Ap = (MODE == 2) ? g_O : A;

    float acc[8][8];
#pragma unroll
    for (int i = 0; i < 8; i++)
#pragma unroll
        for (int j = 0; j < 8; j++) acc[i][j] = 0.0f;

    for (int k0 = 0; k0 < K; k0 += 16) {
        // Load 128x16 A tile and 128x16 B tile, transposed into smem.
#pragma unroll
        for (int it = 0; it < 2; ++it) {
            int lin = tid + it * 256;          // 0..511
            int row = lin >> 2;                // 0..127
            int c4  = (lin & 3) << 2;          // 0,4,8,12
            float4 va = *reinterpret_cast<const float4*>(
                Ap + (size_t)(m0 + row) * K + k0 + c4);
            As[c4 + 0][row] = va.x;
            As[c4 + 1][row] = va.y;
            As[c4 + 2][row] = va.z;
            As[c4 + 3][row] = va.w;
            float4 vb = *reinterpret_cast<const float4*>(
                Bw + (size_t)(n0 + row) * K + k0 + c4);
            Bs[c4 + 0][row] = vb.x;
            Bs[c4 + 1][row] = vb.y;
            Bs[c4 + 2][row] = vb.z;
            Bs[c4 + 3][row] = vb.w;
        }
        __syncthreads();

#pragma unroll
        for (int k = 0; k < 16; k++) {
            float a[8], b[8];
#pragma unroll
            for (int i = 0; i < 8; i++) {
                a[i] = As[k][ty * 8 + i];
                b[i] = Bs[k][tx * 8 + i];
            }
#pragma unroll
            for (int i = 0; i < 8; i++)
#pragma unroll
                for (int j = 0; j < 8; j++) acc[i][j] = fmaf(a[i], b[j], acc[i][j]);
        }
        __syncthreads();
    }

    // Epilogue
#pragma unroll
    for (int i = 0; i < 8; i++) {
        int m = m0 + ty * 8 + i;
        int b = m >> 11;          // m / 2048
        int t = m & 2047;
#pragma unroll
        for (int j = 0; j < 8; j++) {
            int n = n0 + tx * 8 + j;
            float v = acc[i][j];
            if (MODE == 0) {
                int d = n >> 4;
                int h = n & 15;
                g_Q[((((size_t)b * HEADS + h) * SEQ + t) << 6) + d] = v;
            } else if (MODE == 1) {
                int h  = n & 15;
                int kk = (n >> 4) & 1;
                int d  = n >> 5;
                float* dst = kk ? g_V : g_K;
                dst[((((size_t)b * HEADS + h) * SEQ + t) << 6) + d] = v;
            } else {
                C[(size_t)m * N + n] = v;
            }
        }
    }
}

// ---------------------------------------------------------------------------
// Flash attention (fp32). Grid: (SEQ/64, BATCH*HEADS). 256 threads.
// Per CTA: 64 q-rows, loop over 32 key tiles of 64. Online softmax.
// smem layout (pad 68 floats per 64-row; 68%4==0 keeps float4 alignment):
//   Qs[d][r], Ks[d][c], Vs[c][d], Ps[c][r]   each 64*68 floats
// ---------------------------------------------------------------------------
#define TPAD 68
#define TSZ  (64 * TPAD)
#define ATTN_SMEM (4 * TSZ * (int)sizeof(float))

__device__ __forceinline__ void load_tile_T(float* __restrict__ dst,
                                            const float* __restrict__ src,
                                            int tid) {
#pragma unroll
    for (int it = 0; it < 4; ++it) {
        int lin = tid + it * 256;
        int row = lin >> 4;
        int c4  = (lin & 15) << 2;
        float4 v = *reinterpret_cast<const float4*>(src + row * 64 + c4);
        dst[(c4 + 0) * TPAD + row] = v.x;
        dst[(c4 + 1) * TPAD + row] = v.y;
        dst[(c4 + 2) * TPAD + row] = v.z;
        dst[(c4 + 3) * TPAD + row] = v.w;
    }
}

__device__ __forceinline__ void load_tile(float* __restrict__ dst,
                                          const float* __restrict__ src,
                                          int tid) {
#pragma unroll
    for (int it = 0; it < 4; ++it) {
        int lin = tid + it * 256;
        int row = lin >> 4;
        int c4  = (lin & 15) << 2;
        *reinterpret_cast<float4*>(dst + row * TPAD + c4) =
            *reinterpret_cast<const float4*>(src + row * 64 + c4);
    }
}

__global__ __launch_bounds__(256) void attn_kernel() {
    extern __shared__ float sm[];
    float* Qs = sm;              // Qs[d*TPAD + r]
    float* Ks = sm + TSZ;        // Ks[d*TPAD + c]
    float* Vs = sm + 2 * TSZ;    // Vs[c*TPAD + d]
    float* Ps = sm + 3 * TSZ;    // Ps[c*TPAD + r]

    const int tid = threadIdx.x;
    const int ty = tid >> 4;
    const int tx = tid & 15;
    const int r0 = ty << 2;      // 4 q-rows per thread
    const int c0 = tx << 2;      // 4 key-cols / 4 d-cols per thread
    const int bh = blockIdx.y;
    const int t0 = blockIdx.x << 6;

    const float* Qg = g_Q + ((size_t)bh * SEQ + t0) * DHEAD;
    const float* Kg = g_K + (size_t)bh * SEQ * DHEAD;
    const float* Vg = g_V + (size_t)bh * SEQ * DHEAD;

    // Load Q tile (transposed), pre-scaled.
#pragma unroll
    for (int it = 0; it < 4; ++it) {
        int lin = tid + it * 256;
        int row = lin >> 4;
        int c4  = (lin & 15) << 2;
        float4 v = *reinterpret_cast<const float4*>(Qg + row * 64 + c4);
        Qs[(c4 + 0) * TPAD + row] = v.x * SCALE;
        Qs[(c4 + 1) * TPAD + row] = v.y * SCALE;
        Qs[(c4 + 2) * TPAD + row] = v.z * SCALE;
        Qs[(c4 + 3) * TPAD + row] = v.w * SCALE;
    }

    float Oacc[4][4];
#pragma unroll
    for (int i = 0; i < 4; i++)
#pragma unroll
        for (int j = 0; j < 4; j++) Oacc[i][j] = 0.0f;
    float mr[4], lr[4];
#pragma unroll
    for (int i = 0; i < 4; i++) { mr[i] = -1e30f; lr[i] = 0.0f; }

    for (int jt = 0; jt < SEQ / 64; ++jt) {
        load_tile_T(Ks, Kg + (jt << 6) * DHEAD, tid);
        load_tile(Vs, Vg + (jt << 6) * DHEAD, tid);
        __syncthreads();

        // S = Q @ K^T (pre-scaled)
        float Sv[4][4];
#pragma unroll
        for (int i = 0; i < 4; i++)
#pragma unroll
            for (int j = 0; j < 4; j++) Sv[i][j] = 0.0f;
#pragma unroll
        for (int d = 0; d < 64; d++) {
            float a[4], b[4];
#pragma unroll
            for (int i = 0; i < 4; i++) {
                a[i] = Qs[d * TPAD + r0 + i];
                b[i] = Ks[d * TPAD + c0 + i];
            }
#pragma unroll
            for (int i = 0; i < 4; i++)
#pragma unroll
                for (int j = 0; j < 4; j++) Sv[i][j] = fmaf(a[i], b[j], Sv[i][j]);
        }

        // Online softmax per row (reduce across the 16 tx lanes)
#pragma unroll
        for (int i = 0; i < 4; i++) {
            float mx = fmaxf(fmaxf(Sv[i][0], Sv[i][1]), fmaxf(Sv[i][2], Sv[i][3]));
#pragma unroll
            for (int off = 8; off; off >>= 1)
                mx = fmaxf(mx, __shfl_xor_sync(0xffffffffu, mx, off));
            float mnew  = fmaxf(mr[i], mx);
            float alpha = __expf(mr[i] - mnew);
            mr[i] = mnew;
            float ssum = 0.0f;
#pragma unroll
            for (int j = 0; j < 4; j++) {
                float p = __expf(Sv[i][j] - mnew);
                Sv[i][j] = p;
                ssum += p;
            }
#pragma unroll
            for (int off = 8; off; off >>= 1)
                ssum += __shfl_xor_sync(0xffffffffu, ssum, off);
            lr[i] = lr[i] * alpha + ssum;
#pragma unroll
            for (int j = 0; j < 4; j++) Oacc[i][j] *= alpha;
        }

        // Write P transposed: Ps[c][r]
#pragma unroll
        for (int i = 0; i < 4; i++)
#pragma unroll
            for (int j = 0; j < 4; j++)
                Ps[(c0 + j) * TPAD + (r0 + i)] = Sv[i][j];
        __syncthreads();

        // O += P @ V   (tx now indexes d-columns)
#pragma unroll
        for (int c = 0; c < 64; c++) {
            float a[4], b[4];
#pragma unroll
            for (int i = 0; i < 4; i++) {
                a[i] = Ps[c * TPAD + r0 + i];
                b[i] = Vs[c * TPAD + c0 + i];
            }
#pragma unroll
            for (int i = 0; i < 4; i++)
#pragma unroll
                for (int j = 0; j < 4; j++) Oacc[i][j] = fmaf(a[i], b[j], Oacc[i][j]);
        }
        __syncthreads();
    }

    // Normalize and write to g_O[b, t, h*64+d]
    const int b = bh >> 4;
    const int h = bh & 15;
#pragma unroll
    for (int i = 0; i < 4; i++) {
        float inv = 1.0f / lr[i];
        float4 v = make_float4(Oacc[i][0] * inv, Oacc[i][1] * inv,
                               Oacc[i][2] * inv, Oacc[i][3] * inv);
        *reinterpret_cast<float4*>(
            g_O + (size_t)((b * SEQ) + t0 + r0 + i) * EDIM + h * DHEAD + c0) = v;
    }
}

// ---------------------------------------------------------------------------
extern "C" void kernel_launch(void* const* d_in, const int* in_sizes, int n_in,
                              void* d_out, int out_size) {
    const float* q   = (const float*)d_in[0];   // [4,2048,1024]
    const float* kv  = (const float*)d_in[1];   // [4,2048,1024]
    const float* Wq  = (const float*)d_in[2];   // [1024,1024]
    const float* Wkv = (const float*)d_in[3];   // [2048,1024]
    const float* W0  = (const float*)d_in[4];   // [1024,1024]
    float* out = (float*)d_out;                 // [4,2048,1024]

    (void)in_sizes; (void)n_in; (void)out_size;

    (void)cudaFuncSetAttribute(attn_kernel,
                               cudaFuncAttributeMaxDynamicSharedMemorySize,
                               ATTN_SMEM);

    const int M = BATCH * SEQ;  // 8192

    // 1) Q projection -> g_Q[b,h,t,d]
    gemm_tn<0><<<dim3(EDIM / 128, M / 128), 256>>>(q, Wq, nullptr, M, EDIM, DMODEL);
    // 2) KV projection -> g_K, g_V [b,h,t,d]
    gemm_tn<1><<<dim3(2 * EDIM / 128, M / 128), 256>>>(kv, Wkv, nullptr, M, 2 * EDIM, DMODEL);
    // 3) Attention -> g_O[b,t,(h d)]
    attn_kernel<<<dim3(SEQ / 64, BATCH * HEADS), 256, ATTN_SMEM>>>();
    // 4) Output projection -> d_out
    gemm_tn<2><<<dim3(DMODEL / 128, M / 128), 256>>>(nullptr, W0, out, M, DMODEL, EDIM);
}

// round 5
// speedup vs baseline: 1.3505x; 1.3505x over previous
#include <cuda_runtime.h>
#include <cuda_bf16.h>
#include <cstdint>

// Problem constants
#define BATCH   4
#define SEQ     2048
#define DMODEL  1024
#define HEADS   16
#define DHEAD   64
#define EDIM    1024
#define SCALE   0.125f
#define MROWS   (BATCH * SEQ)     // 8192
#define K3      3072              // split-bf16 K' = 3*1024

// ---------------------------------------------------------------------------
// Scratch (device globals; no allocation allowed)
// ---------------------------------------------------------------------------
__device__ __align__(256) float g_Q[(size_t)BATCH * HEADS * SEQ * DHEAD];
__device__ __align__(256) float g_K[(size_t)BATCH * HEADS * SEQ * DHEAD];
__device__ __align__(256) float g_V[(size_t)BATCH * HEADS * SEQ * DHEAD];
// split-bf16 operands: [rows, 3072] = [hi | lo | hi]  (weights: [hi | hi | lo])
__device__ __align__(256) __nv_bfloat16 g_Aq [(size_t)MROWS * K3];
__device__ __align__(256) __nv_bfloat16 g_Akv[(size_t)MROWS * K3];
__device__ __align__(256) __nv_bfloat16 g_Oc [(size_t)MROWS * K3];
__device__ __align__(256) __nv_bfloat16 g_Wqc [(size_t)1024 * K3];
__device__ __align__(256) __nv_bfloat16 g_Wkvc[(size_t)2048 * K3];
__device__ __align__(256) __nv_bfloat16 g_W0c [(size_t)1024 * K3];

// ---------------------------------------------------------------------------
// Helpers (base-ISA only: cp.async, ldmatrix, mma.sync — all compute_100 OK)
// ---------------------------------------------------------------------------
__device__ __forceinline__ uint32_t smem_u32(const void* p) {
    uint32_t a;
    asm("{ .reg .u64 t; cvta.to.shared.u64 t, %1; cvt.u32.u64 %0, t; }" : "=r"(a) : "l"(p));
    return a;
}
__device__ __forceinline__ void cp_async16(uint32_t smem_addr, const void* gptr) {
    asm volatile("cp.async.cg.shared.global [%0], [%1], 16;" :: "r"(smem_addr), "l"(gptr));
}
#define CP_COMMIT() asm volatile("cp.async.commit_group;" ::: "memory")
#define CP_WAIT(n)  asm volatile("cp.async.wait_group %0;" :: "n"(n) : "memory")

__device__ __forceinline__ void ldmatrix_x4(uint32_t& r0, uint32_t& r1, uint32_t& r2,
                                            uint32_t& r3, uint32_t addr) {
    asm volatile("ldmatrix.sync.aligned.m8n8.x4.shared.b16 {%0,%1,%2,%3}, [%4];"
                 : "=r"(r0), "=r"(r1), "=r"(r2), "=r"(r3) : "r"(addr));
}
__device__ __forceinline__ void mma_bf16(float& c0, float& c1, float& c2, float& c3,
                                         uint32_t a0, uint32_t a1, uint32_t a2, uint32_t a3,
                                         uint32_t b0, uint32_t b1) {
    asm volatile(
        "mma.sync.aligned.m16n8k16.row.col.f32.bf16.bf16.f32 "
        "{%0,%1,%2,%3}, {%4,%5,%6,%7}, {%8,%9}, {%0,%1,%2,%3};"
        : "+f"(c0), "+f"(c1), "+f"(c2), "+f"(c3)
        : "r"(a0), "r"(a1), "r"(a2), "r"(a3), "r"(b0), "r"(b1));
}

// ---------------------------------------------------------------------------
// split3: fp32 [R,1024] -> bf16 [R,3072]
// Activations (WHICH 0,1) and attention output use [hi | lo | hi];
// weights (WHICH 2,3,4) use [hi | hi | lo] so products = hh + lh + hl.
// ---------------------------------------------------------------------------
template <int WHICH>
__global__ void split3(const float* __restrict__ src, int total2) {
    __nv_bfloat16* dst = (WHICH == 0) ? g_Aq : (WHICH == 1) ? g_Akv :
                         (WHICH == 2) ? g_Wqc : (WHICH == 3) ? g_Wkvc : g_W0c;
    int idx = blockIdx.x * blockDim.x + threadIdx.x;
    if (idx >= total2) return;
    int r  = idx >> 9;
    int c2 = (idx & 511) << 1;
    float2 v = *reinterpret_cast<const float2*>(src + ((size_t)r << 10) + c2);
    __nv_bfloat16 h0 = __float2bfloat16(v.x), h1 = __float2bfloat16(v.y);
    __nv_bfloat16 l0 = __float2bfloat16(v.x - __bfloat162float(h0));
    __nv_bfloat16 l1 = __float2bfloat16(v.y - __bfloat162float(h1));
    size_t o = (size_t)r * K3;
    __nv_bfloat162 hh = __halves2bfloat162(h0, h1);
    __nv_bfloat162 ll = __halves2bfloat162(l0, l1);
    if (WHICH <= 1) {   // activations: [hi | lo | hi]
        *reinterpret_cast<__nv_bfloat162*>(dst + o + c2)        = hh;
        *reinterpret_cast<__nv_bfloat162*>(dst + o + 1024 + c2) = ll;
        *reinterpret_cast<__nv_bfloat162*>(dst + o + 2048 + c2) = hh;
    } else {            // weights: [hi | hi | lo]
        *reinterpret_cast<__nv_bfloat162*>(dst + o + c2)        = hh;
        *reinterpret_cast<__nv_bfloat162*>(dst + o + 1024 + c2) = hh;
        *reinterpret_cast<__nv_bfloat162*>(dst + o + 2048 + c2) = ll;
    }
}

// ---------------------------------------------------------------------------
// mma.sync bf16 TN GEMM: C[m,n] = sum_k A'[m,k] B'[n,k], K'=3072.
// 128x128 block tile, BK=32, 256 threads = 8 warps (2x4), warp tile 64x32.
// smem rows padded to 40 bf16 (80B): 16B-granular offsets 5r mod 8 distinct
// -> conflict-free ldmatrix. 3-stage cp.async ring.
// MODE 0: A=g_Aq,  B=g_Wqc,  scatter n=(d*16+h)       -> g_Q[b,h,t,d]
// MODE 1: A=g_Akv, B=g_Wkvc, scatter n=(d*32+kk*16+h) -> g_K/g_V
// MODE 2: A=g_Oc,  B=g_W0c,  C[m*1024+n] = v (d_out)
// ---------------------------------------------------------------------------
#define GSTAGES     3
#define NCH         (K3 / 32)            // 96 chunks of BK=32
#define ROWB        80                   // bytes per smem row (40 bf16)
#define TILE_B      (128 * ROWB)         // 10240 per operand tile
#define STAGE_B     (2 * TILE_B)         // 20480
#define GEMM_SMEM   (GSTAGES * STAGE_B)  // 61440

template <int MODE>
__global__ __launch_bounds__(256) void gemm_mma(float* __restrict__ C) {
    extern __shared__ char smem[];
    const uint32_t sb = smem_u32(smem);
    const int tid = threadIdx.x, wid = tid >> 5, lane = tid & 31;
    const int wm = wid >> 2, wn = wid & 3;            // 2 x 4 warp grid
    const int m0 = blockIdx.y * 128, n0 = blockIdx.x * 128;

    const __nv_bfloat16* Ag = (MODE == 0) ? g_Aq : (MODE == 1) ? g_Akv : g_Oc;
    const __nv_bfloat16* Bg = (MODE == 0) ? g_Wqc : (MODE == 1) ? g_Wkvc : g_W0c;
    Ag += (size_t)m0 * K3;
    Bg += (size_t)n0 * K3;

    float acc[4][4][4];
#pragma unroll
    for (int i = 0; i < 4; i++)
#pragma unroll
        for (int j = 0; j < 4; j++)
#pragma unroll
            for (int e = 0; e < 4; e++) acc[i][j][e] = 0.0f;

    auto load_stage = [&](int ch, int s) {
        uint32_t base = sb + s * STAGE_B;
#pragma unroll
        for (int t = 0; t < 2; t++) {
            int idx = tid + t * 256;           // 0..511
            int row = idx >> 2, kc = idx & 3;  // 128 rows x 4 chunks of 8 bf16
            size_t go = (size_t)row * K3 + ch * 32 + kc * 8;
            cp_async16(base + row * ROWB + kc * 16, Ag + go);
            cp_async16(base + TILE_B + row * ROWB + kc * 16, Bg + go);
        }
        CP_COMMIT();
    };

    load_stage(0, 0);
    load_stage(1, 1);
    CP_WAIT(1);
    __syncthreads();

    // Per-lane ldmatrix address components (constant across iterations)
    const uint32_t a_row = (uint32_t)(wm * 64 + (lane & 15));            // m within tile
    const uint32_t a_kb  = (uint32_t)(((lane >> 4) & 1) * 16);           // k byte offset (8 elems)
    const uint32_t b_row = (uint32_t)(wn * 32 + (lane & 7) + ((lane >> 4) & 1) * 8);
    const uint32_t b_kb  = (uint32_t)(((lane >> 3) & 1) * 16);

    for (int ch = 0; ch < NCH; ch++) {
        uint32_t aBase = sb + (ch % GSTAGES) * STAGE_B;
        uint32_t bBase = aBase + TILE_B;
#pragma unroll
        for (int ks = 0; ks < 2; ks++) {
            uint32_t a[4][4], b[4][2];
#pragma unroll
            for (int i = 0; i < 4; i++) {
                uint32_t addr = aBase + (a_row + i * 16) * ROWB + ks * 32 + a_kb;
                ldmatrix_x4(a[i][0], a[i][1], a[i][2], a[i][3], addr);
            }
#pragma unroll
            for (int j2 = 0; j2 < 2; j2++) {
                uint32_t r0, r1, r2, r3;
                uint32_t addr = bBase + (b_row + j2 * 16) * ROWB + ks * 32 + b_kb;
                ldmatrix_x4(r0, r1, r2, r3, addr);
                b[j2 * 2][0] = r0; b[j2 * 2][1] = r1;
                b[j2 * 2 + 1][0] = r2; b[j2 * 2 + 1][1] = r3;
            }
#pragma unroll
            for (int i = 0; i < 4; i++)
#pragma unroll
                for (int j = 0; j < 4; j++)
                    mma_bf16(acc[i][j][0], acc[i][j][1], acc[i][j][2], acc[i][j][3],
                             a[i][0], a[i][1], a[i][2], a[i][3], b[j][0], b[j][1]);
        }
        if (ch + 2 < NCH) {
            load_stage(ch + 2, (ch + 2) % GSTAGES);
            CP_WAIT(1);
        } else {
            CP_WAIT(0);
        }
        __syncthreads();
    }

    // Epilogue scatter
    const int g = lane >> 2, tq = lane & 3;
#pragma unroll
    for (int i = 0; i < 4; i++) {
#pragma unroll
        for (int e = 0; e < 2; e++) {       // row half: +0 / +8
            int m = m0 + wm * 64 + i * 16 + g + e * 8;
            int b = m >> 11;
            int t = m & 2047;
#pragma unroll
            for (int j = 0; j < 4; j++) {
#pragma unroll
                for (int x = 0; x < 2; x++) {
                    int n = n0 + wn * 32 + j * 8 + tq * 2 + x;
                    float v = acc[i][j][e * 2 + x];
                    if (MODE == 0) {
                        int d = n >> 4, h = n & 15;
                        g_Q[((((size_t)b * HEADS + h) * SEQ + t) << 6) + d] = v;
                    } else if (MODE == 1) {
                        int h = n & 15, kk = (n >> 4) & 1, d = n >> 5;
                        float* dst = kk ? g_V : g_K;
                        dst[((((size_t)b * HEADS + h) * SEQ + t) << 6) + d] = v;
                    } else {
                        C[(size_t)m * 1024 + n] = v;
                    }
                }
            }
        }
    }
}

// ---------------------------------------------------------------------------
// Flash attention (fp32); epilogue writes split-bf16 [hi|lo|hi] into g_Oc.
// ---------------------------------------------------------------------------
#define TPAD 68
#define TSZ  (64 * TPAD)
#define ATTN_SMEM (4 * TSZ * (int)sizeof(float))

__device__ __forceinline__ void load_tile_T(float* __restrict__ dst,
                                            const float* __restrict__ src, int tid) {
#pragma unroll
    for (int it = 0; it < 4; ++it) {
        int lin = tid + it * 256;
        int row = lin >> 4;
        int c4  = (lin & 15) << 2;
        float4 v = *reinterpret_cast<const float4*>(src + row * 64 + c4);
        dst[(c4 + 0) * TPAD + row] = v.x;
        dst[(c4 + 1) * TPAD + row] = v.y;
        dst[(c4 + 2) * TPAD + row] = v.z;
        dst[(c4 + 3) * TPAD + row] = v.w;
    }
}
__device__ __forceinline__ void load_tile(float* __restrict__ dst,
                                          const float* __restrict__ src, int tid) {
#pragma unroll
    for (int it = 0; it < 4; ++it) {
        int lin = tid + it * 256;
        int row = lin >> 4;
        int c4  = (lin & 15) << 2;
        *reinterpret_cast<float4*>(dst + row * TPAD + c4) =
            *reinterpret_cast<const float4*>(src + row * 64 + c4);
    }
}

__global__ __launch_bounds__(256) void attn_kernel() {
    extern __shared__ float sm[];
    float* Qs = sm;
    float* Ks = sm + TSZ;
    float* Vs = sm + 2 * TSZ;
    float* Ps = sm + 3 * TSZ;

    const int tid = threadIdx.x;
    const int ty = tid >> 4;
    const int tx = tid & 15;
    const int r0 = ty << 2;
    const int c0 = tx << 2;
    const int bh = blockIdx.y;
    const int t0 = blockIdx.x << 6;

    const float* Qg = g_Q + ((size_t)bh * SEQ + t0) * DHEAD;
    const float* Kg = g_K + (size_t)bh * SEQ * DHEAD;
    const float* Vg = g_V + (size_t)bh * SEQ * DHEAD;

#pragma unroll
    for (int it = 0; it < 4; ++it) {
        int lin = tid + it * 256;
        int row = lin >> 4;
        int c4  = (lin & 15) << 2;
        float4 v = *reinterpret_cast<const float4*>(Qg + row * 64 + c4);
        Qs[(c4 + 0) * TPAD + row] = v.x * SCALE;
        Qs[(c4 + 1) * TPAD + row] = v.y * SCALE;
        Qs[(c4 + 2) * TPAD + row] = v.z * SCALE;
        Qs[(c4 + 3) * TPAD + row] = v.w * SCALE;
    }

    float Oacc[4][4];
#pragma unroll
    for (int i = 0; i < 4; i++)
#pragma unroll
        for (int j = 0; j < 4; j++) Oacc[i][j] = 0.0f;
    float mr[4], lr[4];
#pragma unroll
    for (int i = 0; i < 4; i++) { mr[i] = -1e30f; lr[i] = 0.0f; }

    for (int jt = 0; jt < SEQ / 64; ++jt) {
        load_tile_T(Ks, Kg + (jt << 6) * DHEAD, tid);
        load_tile(Vs, Vg + (jt << 6) * DHEAD, tid);
        __syncthreads();

        float Sv[4][4];
#pragma unroll
        for (int i = 0; i < 4; i++)
#pragma unroll
            for (int j = 0; j < 4; j++) Sv[i][j] = 0.0f;
#pragma unroll
        for (int d = 0; d < 64; d++) {
            float a[4], b[4];
#pragma unroll
            for (int i = 0; i < 4; i++) {
                a[i] = Qs[d * TPAD + r0 + i];
                b[i] = Ks[d * TPAD + c0 + i];
            }
#pragma unroll
            for (int i = 0; i < 4; i++)
#pragma unroll
                for (int j = 0; j < 4; j++) Sv[i][j] = fmaf(a[i], b[j], Sv[i][j]);
        }

#pragma unroll
        for (int i = 0; i < 4; i++) {
            float mx = fmaxf(fmaxf(Sv[i][0], Sv[i][1]), fmaxf(Sv[i][2], Sv[i][3]));
#pragma unroll
            for (int off = 8; off; off >>= 1)
                mx = fmaxf(mx, __shfl_xor_sync(0xffffffffu, mx, off));
            float mnew  = fmaxf(mr[i], mx);
            float alpha = __expf(mr[i] - mnew);
            mr[i] = mnew;
            float ssum = 0.0f;
#pragma unroll
            for (int j = 0; j < 4; j++) {
                float p = __expf(Sv[i][j] - mnew);
                Sv[i][j] = p;
                ssum += p;
            }
#pragma unroll
            for (int off = 8; off; off >>= 1)
                ssum += __shfl_xor_sync(0xffffffffu, ssum, off);
            lr[i] = lr[i] * alpha + ssum;
#pragma unroll
            for (int j = 0; j < 4; j++) Oacc[i][j] *= alpha;
        }

#pragma unroll
        for (int i = 0; i < 4; i++)
#pragma unroll
            for (int j = 0; j < 4; j++)
                Ps[(c0 + j) * TPAD + (r0 + i)] = Sv[i][j];
        __syncthreads();

#pragma unroll
        for (int c = 0; c < 64; c++) {
            float a[4], b[4];
#pragma unroll
            for (int i = 0; i < 4; i++) {
                a[i] = Ps[c * TPAD + r0 + i];
                b[i] = Vs[c * TPAD + c0 + i];
            }
#pragma unroll
            for (int i = 0; i < 4; i++)
#pragma unroll
                for (int j = 0; j < 4; j++) Oacc[i][j] = fmaf(a[i], b[j], Oacc[i][j]);
        }
        __syncthreads();
    }

    // Epilogue: write split-bf16 [hi|lo|hi] rows of g_Oc
    const int bq = bh >> 4;
    const int h = bh & 15;
#pragma unroll
    for (int i = 0; i < 4; i++) {
        float inv = 1.0f / lr[i];
        size_t row = (size_t)(bq * SEQ + t0 + r0 + i);
        int col = h * DHEAD + c0;
        __nv_bfloat16 hi[4], lo[4];
#pragma unroll
        for (int j = 0; j < 4; j++) {
            float v = Oacc[i][j] * inv;
            hi[j] = __float2bfloat16(v);
            lo[j] = __float2bfloat16(v - __bfloat162float(hi[j]));
        }
        __nv_bfloat162 h01 = __halves2bfloat162(hi[0], hi[1]);
        __nv_bfloat162 h23 = __halves2bfloat162(hi[2], hi[3]);
        __nv_bfloat162 l01 = __halves2bfloat162(lo[0], lo[1]);
        __nv_bfloat162 l23 = __halves2bfloat162(lo[2], lo[3]);
        __nv_bfloat162* p0 = reinterpret_cast<__nv_bfloat162*>(g_Oc + row * K3 + col);
        __nv_bfloat162* p1 = reinterpret_cast<__nv_bfloat162*>(g_Oc + row * K3 + 1024 + col);
        __nv_bfloat162* p2 = reinterpret_cast<__nv_bfloat162*>(g_Oc + row * K3 + 2048 + col);
        p0[0] = h01; p0[1] = h23;
        p1[0] = l01; p1[1] = l23;
        p2[0] = h01; p2[1] = h23;
    }
}

// ---------------------------------------------------------------------------
extern "C" void kernel_launch(void* const* d_in, const int* in_sizes, int n_in,
                              void* d_out, int out_size) {
    const float* q   = (const float*)d_in[0];
    const float* kv  = (const float*)d_in[1];
    const float* Wq  = (const float*)d_in[2];
    const float* Wkv = (const float*)d_in[3];
    const float* W0  = (const float*)d_in[4];
    float* out = (float*)d_out;
    (void)in_sizes; (void)n_in; (void)out_size;

    (void)cudaFuncSetAttribute(attn_kernel, cudaFuncAttributeMaxDynamicSharedMemorySize, ATTN_SMEM);
    (void)cudaFuncSetAttribute(gemm_mma<0>, cudaFuncAttributeMaxDynamicSharedMemorySize, GEMM_SMEM);
    (void)cudaFuncSetAttribute(gemm_mma<1>, cudaFuncAttributeMaxDynamicSharedMemorySize, GEMM_SMEM);
    (void)cudaFuncSetAttribute(gemm_mma<2>, cudaFuncAttributeMaxDynamicSharedMemorySize, GEMM_SMEM);

    // Split conversions (activations + weights)
    split3<0><<<(MROWS * 512 + 255) / 256, 256>>>(q,   MROWS * 512);
    split3<1><<<(MROWS * 512 + 255) / 256, 256>>>(kv,  MROWS * 512);
    split3<2><<<(1024 * 512 + 255) / 256, 256>>>(Wq,  1024 * 512);
    split3<3><<<(2048 * 512 + 255) / 256, 256>>>(Wkv, 2048 * 512);
    split3<4><<<(1024 * 512 + 255) / 256, 256>>>(W0,  1024 * 512);

    // Projections on tensor cores (mma.sync)
    gemm_mma<0><<<dim3(EDIM / 128, MROWS / 128), 256, GEMM_SMEM>>>(nullptr);
    gemm_mma<1><<<dim3(2 * EDIM / 128, MROWS / 128), 256, GEMM_SMEM>>>(nullptr);
    // Attention (fp32) -> g_Oc split-bf16
    attn_kernel<<<dim3(SEQ / 64, BATCH * HEADS), 256, ATTN_SMEM>>>();
    // Output projection on tensor cores
    gemm_mma<2><<<dim3(DMODEL / 128, MROWS / 128), 256, GEMM_SMEM>>>(out);
}

// round 7
// speedup vs baseline: 2.2302x; 1.6513x over previous
#include <cuda_runtime.h>
#include <cuda_bf16.h>
#include <cstdint>

// Problem constants
#define BATCH   4
#define SEQ     2048
#define DMODEL  1024
#define HEADS   16
#define DHEAD   64
#define EDIM    1024
#define MROWS   (BATCH * SEQ)     // 8192
#define K3      3072              // split-bf16 K' = 3*1024

// ---------------------------------------------------------------------------
// Scratch (device globals; no allocation allowed)
// ---------------------------------------------------------------------------
// Attention operands, [b,h,t,d] bf16 hi/lo.  Q pre-scaled by 0.125.
__device__ __align__(256) __nv_bfloat16 g_Qh[(size_t)BATCH * HEADS * SEQ * DHEAD];
__device__ __align__(256) __nv_bfloat16 g_Ql[(size_t)BATCH * HEADS * SEQ * DHEAD];
__device__ __align__(256) __nv_bfloat16 g_Kh[(size_t)BATCH * HEADS * SEQ * DHEAD];
__device__ __align__(256) __nv_bfloat16 g_Kl[(size_t)BATCH * HEADS * SEQ * DHEAD];
__device__ __align__(256) __nv_bfloat16 g_Vh[(size_t)BATCH * HEADS * SEQ * DHEAD];
__device__ __align__(256) __nv_bfloat16 g_Vl[(size_t)BATCH * HEADS * SEQ * DHEAD];
// split-bf16 GEMM operands: [rows, 3072]
__device__ __align__(256) __nv_bfloat16 g_Aq [(size_t)MROWS * K3];
__device__ __align__(256) __nv_bfloat16 g_Akv[(size_t)MROWS * K3];
__device__ __align__(256) __nv_bfloat16 g_Oc [(size_t)MROWS * K3];
__device__ __align__(256) __nv_bfloat16 g_Wqc [(size_t)1024 * K3];
__device__ __align__(256) __nv_bfloat16 g_Wkvc[(size_t)2048 * K3];
__device__ __align__(256) __nv_bfloat16 g_W0c [(size_t)1024 * K3];

// ---------------------------------------------------------------------------
// Helpers (base-ISA: cp.async, ldmatrix, mma.sync)
// ---------------------------------------------------------------------------
__device__ __forceinline__ uint32_t smem_u32(const void* p) {
    uint32_t a;
    asm("{ .reg .u64 t; cvta.to.shared.u64 t, %1; cvt.u32.u64 %0, t; }" : "=r"(a) : "l"(p));
    return a;
}
__device__ __forceinline__ void cp_async16(uint32_t smem_addr, const void* gptr) {
    asm volatile("cp.async.cg.shared.global [%0], [%1], 16;" :: "r"(smem_addr), "l"(gptr));
}
#define CP_COMMIT() asm volatile("cp.async.commit_group;" ::: "memory")
#define CP_WAIT(n)  asm volatile("cp.async.wait_group %0;" :: "n"(n) : "memory")

__device__ __forceinline__ void ldmatrix_x4(uint32_t& r0, uint32_t& r1, uint32_t& r2,
                                            uint32_t& r3, uint32_t addr) {
    asm volatile("ldmatrix.sync.aligned.m8n8.x4.shared.b16 {%0,%1,%2,%3}, [%4];"
                 : "=r"(r0), "=r"(r1), "=r"(r2), "=r"(r3) : "r"(addr));
}
__device__ __forceinline__ void ldmatrix_x4_trans(uint32_t& r0, uint32_t& r1, uint32_t& r2,
                                                  uint32_t& r3, uint32_t addr) {
    asm volatile("ldmatrix.sync.aligned.m8n8.x4.trans.shared.b16 {%0,%1,%2,%3}, [%4];"
                 : "=r"(r0), "=r"(r1), "=r"(r2), "=r"(r3) : "r"(addr));
}
__device__ __forceinline__ void mma_bf16(float* c,
                                         uint32_t a0, uint32_t a1, uint32_t a2, uint32_t a3,
                                         uint32_t b0, uint32_t b1) {
    asm volatile(
        "mma.sync.aligned.m16n8k16.row.col.f32.bf16.bf16.f32 "
        "{%0,%1,%2,%3}, {%4,%5,%6,%7}, {%8,%9}, {%0,%1,%2,%3};"
        : "+f"(c[0]), "+f"(c[1]), "+f"(c[2]), "+f"(c[3])
        : "r"(a0), "r"(a1), "r"(a2), "r"(a3), "r"(b0), "r"(b1));
}
__device__ __forceinline__ uint32_t pack_bf16x2(float x, float y) {
    __nv_bfloat162 t = __halves2bfloat162(__float2bfloat16(x), __float2bfloat16(y));
    return *reinterpret_cast<uint32_t*>(&t);
}

// ---------------------------------------------------------------------------
// split3: fp32 [R,1024] -> bf16 [R,3072]
// activations (0,1): [hi | lo | hi];  weights (2,3,4): [hi | hi | lo]
// ---------------------------------------------------------------------------
template <int WHICH>
__global__ void split3(const float* __restrict__ src, int total2) {
    __nv_bfloat16* dst = (WHICH == 0) ? g_Aq : (WHICH == 1) ? g_Akv :
                         (WHICH == 2) ? g_Wqc : (WHICH == 3) ? g_Wkvc : g_W0c;
    int idx = blockIdx.x * blockDim.x + threadIdx.x;
    if (idx >= total2) return;
    int r  = idx >> 9;
    int c2 = (idx & 511) << 1;
    float2 v = *reinterpret_cast<const float2*>(src + ((size_t)r << 10) + c2);
    __nv_bfloat16 h0 = __float2bfloat16(v.x), h1 = __float2bfloat16(v.y);
    __nv_bfloat16 l0 = __float2bfloat16(v.x - __bfloat162float(h0));
    __nv_bfloat16 l1 = __float2bfloat16(v.y - __bfloat162float(h1));
    size_t o = (size_t)r * K3;
    __nv_bfloat162 hh = __halves2bfloat162(h0, h1);
    __nv_bfloat162 ll = __halves2bfloat162(l0, l1);
    if (WHICH <= 1) {
        *reinterpret_cast<__nv_bfloat162*>(dst + o + c2)        = hh;
        *reinterpret_cast<__nv_bfloat162*>(dst + o + 1024 + c2) = ll;
        *reinterpret_cast<__nv_bfloat162*>(dst + o + 2048 + c2) = hh;
    } else {
        *reinterpret_cast<__nv_bfloat162*>(dst + o + c2)        = hh;
        *reinterpret_cast<__nv_bfloat162*>(dst + o + 1024 + c2) = hh;
        *reinterpret_cast<__nv_bfloat162*>(dst + o + 2048 + c2) = ll;
    }
}

// ---------------------------------------------------------------------------
// mma.sync bf16 TN GEMM, 128x128 tile, BK=32, 8 warps (2x4), warp 64x32.
// MODE 0: scatter n=(d*16+h) -> g_Qh/g_Ql (pre-scaled 0.125)
// MODE 1: scatter n=(d*32+kk*16+h) -> g_Kh/g_Kl or g_Vh/g_Vl
// MODE 2: C[m*1024+n] = v (d_out)
// ---------------------------------------------------------------------------
#define GSTAGES     3
#define NCH         (K3 / 32)            // 96
#define ROWB        80
#define TILE_B      (128 * ROWB)
#define STAGE_B     (2 * TILE_B)
#define GEMM_SMEM   (GSTAGES * STAGE_B)  // 61440

template <int MODE>
__global__ __launch_bounds__(256) void gemm_mma(float* __restrict__ C) {
    extern __shared__ char smem[];
    const uint32_t sb = smem_u32(smem);
    const int tid = threadIdx.x, wid = tid >> 5, lane = tid & 31;
    const int wm = wid >> 2, wn = wid & 3;
    const int m0 = blockIdx.y * 128, n0 = blockIdx.x * 128;

    const __nv_bfloat16* Ag = (MODE == 0) ? g_Aq : (MODE == 1) ? g_Akv : g_Oc;
    const __nv_bfloat16* Bg = (MODE == 0) ? g_Wqc : (MODE == 1) ? g_Wkvc : g_W0c;
    Ag += (size_t)m0 * K3;
    Bg += (size_t)n0 * K3;

    float acc[4][4][4];
#pragma unroll
    for (int i = 0; i < 4; i++)
#pragma unroll
        for (int j = 0; j < 4; j++)
#pragma unroll
            for (int e = 0; e < 4; e++) acc[i][j][e] = 0.0f;

    auto load_stage = [&](int ch, int s) {
        uint32_t base = sb + s * STAGE_B;
#pragma unroll
        for (int t = 0; t < 2; t++) {
            int idx = tid + t * 256;
            int row = idx >> 2, kc = idx & 3;
            size_t go = (size_t)row * K3 + ch * 32 + kc * 8;
            cp_async16(base + row * ROWB + kc * 16, Ag + go);
            cp_async16(base + TILE_B + row * ROWB + kc * 16, Bg + go);
        }
        CP_COMMIT();
    };

    load_stage(0, 0);
    load_stage(1, 1);
    CP_WAIT(1);
    __syncthreads();

    const uint32_t a_row = (uint32_t)(wm * 64 + (lane & 15));
    const uint32_t a_kb  = (uint32_t)(((lane >> 4) & 1) * 16);
    const uint32_t b_row = (uint32_t)(wn * 32 + (lane & 7) + ((lane >> 4) & 1) * 8);
    const uint32_t b_kb  = (uint32_t)(((lane >> 3) & 1) * 16);

    for (int ch = 0; ch < NCH; ch++) {
        uint32_t aBase = sb + (ch % GSTAGES) * STAGE_B;
        uint32_t bBase = aBase + TILE_B;
#pragma unroll
        for (int ks = 0; ks < 2; ks++) {
            uint32_t a[4][4], b[4][2];
#pragma unroll
            for (int i = 0; i < 4; i++) {
                uint32_t addr = aBase + (a_row + i * 16) * ROWB + ks * 32 + a_kb;
                ldmatrix_x4(a[i][0], a[i][1], a[i][2], a[i][3], addr);
            }
#pragma unroll
            for (int j2 = 0; j2 < 2; j2++) {
                uint32_t r0, r1, r2, r3;
                uint32_t addr = bBase + (b_row + j2 * 16) * ROWB + ks * 32 + b_kb;
                ldmatrix_x4(r0, r1, r2, r3, addr);
                b[j2 * 2][0] = r0; b[j2 * 2][1] = r1;
                b[j2 * 2 + 1][0] = r2; b[j2 * 2 + 1][1] = r3;
            }
#pragma unroll
            for (int i = 0; i < 4; i++)
#pragma unroll
                for (int j = 0; j < 4; j++)
                    mma_bf16(acc[i][j], a[i][0], a[i][1], a[i][2], a[i][3], b[j][0], b[j][1]);
        }
        if (ch + 2 < NCH) {
            load_stage(ch + 2, (ch + 2) % GSTAGES);
            CP_WAIT(1);
        } else {
            CP_WAIT(0);
        }
        __syncthreads();
    }

    const int g = lane >> 2, tq = lane & 3;
#pragma unroll
    for (int i = 0; i < 4; i++) {
#pragma unroll
        for (int e = 0; e < 2; e++) {
            int m = m0 + wm * 64 + i * 16 + g + e * 8;
            int b = m >> 11;
            int t = m & 2047;
#pragma unroll
            for (int j = 0; j < 4; j++) {
#pragma unroll
                for (int x = 0; x < 2; x++) {
                    int n = n0 + wn * 32 + j * 8 + tq * 2 + x;
                    float v = acc[i][j][e * 2 + x];
                    if (MODE == 0) {
                        int d = n >> 4, h = n & 15;
                        size_t a5 = ((((size_t)b * HEADS + h) * SEQ + t) << 6) + d;
                        float vs = v * 0.125f;
                        __nv_bfloat16 hi = __float2bfloat16(vs);
                        g_Qh[a5] = hi;
                        g_Ql[a5] = __float2bfloat16(vs - __bfloat162float(hi));
                    } else if (MODE == 1) {
                        int h = n & 15, kk = (n >> 4) & 1, d = n >> 5;
                        size_t a5 = ((((size_t)b * HEADS + h) * SEQ + t) << 6) + d;
                        __nv_bfloat16 hi = __float2bfloat16(v);
                        __nv_bfloat16 lo = __float2bfloat16(v - __bfloat162float(hi));
                        if (kk) { g_Vh[a5] = hi; g_Vl[a5] = lo; }
                        else    { g_Kh[a5] = hi; g_Kl[a5] = lo; }
                    } else {
                        C[(size_t)m * 1024 + n] = v;
                    }
                }
            }
        }
    }
}

// ---------------------------------------------------------------------------
// Flash attention on mma.sync. CTA: 128 q-rows, 8 warps (m16 each), key
// tiles of 64, double-buffered K/V stages. 3-term split for QK and PV.
// smem stage: Kh|Kl|Vh|Vl, each 64 rows x 144B (72 bf16, padded).
// ---------------------------------------------------------------------------
#define AROWB    144
#define ATILE_B  (64 * AROWB)            // 9216
#define ASTAGE_B (4 * ATILE_B)           // 36864
#define ATTN_SMEM (2 * ASTAGE_B)         // 73728

__global__ __launch_bounds__(256) void attn_mma() {
    extern __shared__ char smem[];
    const uint32_t sb = smem_u32(smem);
    const int tid = threadIdx.x, wid = tid >> 5, lane = tid & 31;
    const int g = lane >> 2, tq = lane & 3;
    const int bh = blockIdx.y;
    const int t0 = blockIdx.x << 7;          // 128 q-rows per CTA

    const size_t bhoff = (size_t)bh * SEQ * DHEAD;
    const __nv_bfloat16* Qh = g_Qh + bhoff + (size_t)t0 * DHEAD;
    const __nv_bfloat16* Ql = g_Ql + bhoff + (size_t)t0 * DHEAD;
    const __nv_bfloat16* Kh = g_Kh + bhoff;
    const __nv_bfloat16* Kl = g_Kl + bhoff;
    const __nv_bfloat16* Vh = g_Vh + bhoff;
    const __nv_bfloat16* Vl = g_Vl + bhoff;

    // ---- Stage Q (hi at offset 0, lo at offset 2*ATILE_B) and extract frags
#pragma unroll
    for (int t = 0; t < 8; t++) {
        int idx = tid + t * 256;             // 0..2047
        int mat = idx >> 10;                 // 0=hi,1=lo
        int r   = (idx >> 3) & 127;
        int ck  = idx & 7;
        const __nv_bfloat16* src = mat ? Ql : Qh;
        cp_async16(sb + mat * (2 * ATILE_B) + r * AROWB + ck * 16,
                   src + (size_t)r * DHEAD + ck * 8);
    }
    CP_COMMIT();
    CP_WAIT(0);
    __syncthreads();

    uint32_t qh[4][4], ql[4][4];
    {
        uint32_t qrow = (uint32_t)(wid * 16 + (lane & 15));
        uint32_t kb   = (uint32_t)(((lane >> 4) & 1) * 16);
#pragma unroll
        for (int ks = 0; ks < 4; ks++) {
            uint32_t addr = sb + qrow * AROWB + ks * 32 + kb;
            ldmatrix_x4(qh[ks][0], qh[ks][1], qh[ks][2], qh[ks][3], addr);
            ldmatrix_x4(ql[ks][0], ql[ks][1], ql[ks][2], ql[ks][3],
                        addr + 2 * ATILE_B);
        }
    }
    __syncthreads();

    // ---- K/V tile loader
    auto load_kv = [&](int jt, int s) {
        uint32_t base = sb + s * ASTAGE_B;
        const __nv_bfloat16* ptrs[4] = {Kh, Kl, Vh, Vl};
#pragma unroll
        for (int t = 0; t < 8; t++) {
            int idx = tid + t * 256;         // 0..2047
            int mat = idx >> 9;              // 0..3
            int r   = (idx >> 3) & 63;
            int ck  = idx & 7;
            cp_async16(base + mat * ATILE_B + r * AROWB + ck * 16,
                       ptrs[mat] + (size_t)(jt * 64 + r) * DHEAD + ck * 8);
        }
        CP_COMMIT();
    };

    load_kv(0, 0);
    load_kv(1, 1);

    float oacc[8][4];
#pragma unroll
    for (int j = 0; j < 8; j++)
#pragma unroll
        for (int e = 0; e < 4; e++) oacc[j][e] = 0.0f;
    float mr0 = -1e30f, mr1 = -1e30f, lr0 = 0.0f, lr1 = 0.0f;

    const uint32_t kb_row = (uint32_t)((lane & 7) + ((lane >> 4) & 1) * 8);
    const uint32_t kb_kb  = (uint32_t)(((lane >> 3) & 1) * 16);
    const uint32_t v_row  = (uint32_t)((lane & 7) + ((lane >> 3) & 1) * 8);
    const uint32_t v_cb   = (uint32_t)(((lane >> 4) & 1) * 8 * 2);

    for (int jt = 0; jt < SEQ / 64; jt++) {
        if (jt + 1 < SEQ / 64) { CP_WAIT(1); } else { CP_WAIT(0); }
        __syncthreads();
        uint32_t st = sb + (jt & 1) * ASTAGE_B;

        // ---- S = Qh*Kh + Ql*Kh + Qh*Kl
        float sacc[8][4];
#pragma unroll
        for (int j = 0; j < 8; j++)
#pragma unroll
            for (int e = 0; e < 4; e++) sacc[j][e] = 0.0f;
#pragma unroll
        for (int ks = 0; ks < 4; ks++) {
            uint32_t bt[8][2];
#pragma unroll
            for (int j2 = 0; j2 < 4; j2++) {
                uint32_t r0, r1, r2, r3;
                uint32_t addr = st + (kb_row + j2 * 16) * AROWB + ks * 32 + kb_kb;
                ldmatrix_x4(r0, r1, r2, r3, addr);
                bt[j2 * 2][0] = r0; bt[j2 * 2][1] = r1;
                bt[j2 * 2 + 1][0] = r2; bt[j2 * 2 + 1][1] = r3;
            }
#pragma unroll
            for (int j = 0; j < 8; j++)
                mma_bf16(sacc[j], qh[ks][0], qh[ks][1], qh[ks][2], qh[ks][3],
                         bt[j][0], bt[j][1]);
#pragma unroll
            for (int j = 0; j < 8; j++)
                mma_bf16(sacc[j], ql[ks][0], ql[ks][1], ql[ks][2], ql[ks][3],
                         bt[j][0], bt[j][1]);
#pragma unroll
            for (int j2 = 0; j2 < 4; j2++) {
                uint32_t r0, r1, r2, r3;
                uint32_t addr = st + ATILE_B + (kb_row + j2 * 16) * AROWB + ks * 32 + kb_kb;
                ldmatrix_x4(r0, r1, r2, r3, addr);
                bt[j2 * 2][0] = r0; bt[j2 * 2][1] = r1;
                bt[j2 * 2 + 1][0] = r2; bt[j2 * 2 + 1][1] = r3;
            }
#pragma unroll
            for (int j = 0; j < 8; j++)
                mma_bf16(sacc[j], qh[ks][0], qh[ks][1], qh[ks][2], qh[ks][3],
                         bt[j][0], bt[j][1]);
        }

        // ---- online softmax (two row-halves per thread)
        float mx0 = -1e30f, mx1 = -1e30f;
#pragma unroll
        for (int j = 0; j < 8; j++) {
            mx0 = fmaxf(mx0, fmaxf(sacc[j][0], sacc[j][1]));
            mx1 = fmaxf(mx1, fmaxf(sacc[j][2], sacc[j][3]));
        }
        mx0 = fmaxf(mx0, __shfl_xor_sync(0xffffffffu, mx0, 1));
        mx0 = fmaxf(mx0, __shfl_xor_sync(0xffffffffu, mx0, 2));
        mx1 = fmaxf(mx1, __shfl_xor_sync(0xffffffffu, mx1, 1));
        mx1 = fmaxf(mx1, __shfl_xor_sync(0xffffffffu, mx1, 2));
        float mn0 = fmaxf(mr0, mx0), mn1 = fmaxf(mr1, mx1);
        float al0 = __expf(mr0 - mn0), al1 = __expf(mr1 - mn1);
        mr0 = mn0; mr1 = mn1;
        float sum0 = 0.0f, sum1 = 0.0f;
#pragma unroll
        for (int j = 0; j < 8; j++) {
            sacc[j][0] = __expf(sacc[j][0] - mn0);
            sacc[j][1] = __expf(sacc[j][1] - mn0);
            sacc[j][2] = __expf(sacc[j][2] - mn1);
            sacc[j][3] = __expf(sacc[j][3] - mn1);
            sum0 += sacc[j][0] + sacc[j][1];
            sum1 += sacc[j][2] + sacc[j][3];
        }
        sum0 += __shfl_xor_sync(0xffffffffu, sum0, 1);
        sum0 += __shfl_xor_sync(0xffffffffu, sum0, 2);
        sum1 += __shfl_xor_sync(0xffffffffu, sum1, 1);
        sum1 += __shfl_xor_sync(0xffffffffu, sum1, 2);
        lr0 = lr0 * al0 + sum0;
        lr1 = lr1 * al1 + sum1;
#pragma unroll
        for (int j = 0; j < 8; j++) {
            oacc[j][0] *= al0; oacc[j][1] *= al0;
            oacc[j][2] *= al1; oacc[j][3] *= al1;
        }

        // ---- O += Ph*Vh + Pl*Vh + Ph*Vl
#pragma unroll
        for (int cs = 0; cs < 4; cs++) {
            int j0 = cs * 2, j1 = cs * 2 + 1;
            uint32_t ph[4], pl[4];
            {
                float p00 = sacc[j0][0], p01 = sacc[j0][1];
                float p02 = sacc[j0][2], p03 = sacc[j0][3];
                float p10 = sacc[j1][0], p11 = sacc[j1][1];
                float p12 = sacc[j1][2], p13 = sacc[j1][3];
                ph[0] = pack_bf16x2(p00, p01);
                ph[1] = pack_bf16x2(p02, p03);
                ph[2] = pack_bf16x2(p10, p11);
                ph[3] = pack_bf16x2(p12, p13);
                __nv_bfloat162 h;
                h = *reinterpret_cast<__nv_bfloat162*>(&ph[0]);
                pl[0] = pack_bf16x2(p00 - __bfloat162float(h.x), p01 - __bfloat162float(h.y));
                h = *reinterpret_cast<__nv_bfloat162*>(&ph[1]);
                pl[1] = pack_bf16x2(p02 - __bfloat162float(h.x), p03 - __bfloat162float(h.y));
                h = *reinterpret_cast<__nv_bfloat162*>(&ph[2]);
                pl[2] = pack_bf16x2(p10 - __bfloat162float(h.x), p11 - __bfloat162float(h.y));
                h = *reinterpret_cast<__nv_bfloat162*>(&ph[3]);
                pl[3] = pack_bf16x2(p12 - __bfloat162float(h.x), p13 - __bfloat162float(h.y));
            }
            uint32_t vt[8][2];
#pragma unroll
            for (int jd2 = 0; jd2 < 4; jd2++) {
                uint32_t r0, r1, r2, r3;
                uint32_t addr = st + 2 * ATILE_B + (cs * 16 + v_row) * AROWB
                              + jd2 * 32 + v_cb;
                ldmatrix_x4_trans(r0, r1, r2, r3, addr);
                vt[jd2 * 2][0] = r0; vt[jd2 * 2][1] = r1;
                vt[jd2 * 2 + 1][0] = r2; vt[jd2 * 2 + 1][1] = r3;
            }
#pragma unroll
            for (int jd = 0; jd < 8; jd++)
                mma_bf16(oacc[jd], ph[0], ph[1], ph[2], ph[3], vt[jd][0], vt[jd][1]);
#pragma unroll
            for (int jd = 0; jd < 8; jd++)
                mma_bf16(oacc[jd], pl[0], pl[1], pl[2], pl[3], vt[jd][0], vt[jd][1]);
#pragma unroll
            for (int jd2 = 0; jd2 < 4; jd2++) {
                uint32_t r0, r1, r2, r3;
                uint32_t addr = st + 3 * ATILE_B + (cs * 16 + v_row) * AROWB
                              + jd2 * 32 + v_cb;
                ldmatrix_x4_trans(r0, r1, r2, r3, addr);
                vt[jd2 * 2][0] = r0; vt[jd2 * 2][1] = r1;
                vt[jd2 * 2 + 1][0] = r2; vt[jd2 * 2 + 1][1] = r3;
            }
#pragma unroll
            for (int jd = 0; jd < 8; jd++)
                mma_bf16(oacc[jd], ph[0], ph[1], ph[2], ph[3], vt[jd][0], vt[jd][1]);
        }

        __syncthreads();
        if (jt + 2 < SEQ / 64) load_kv(jt + 2, jt & 1);
    }

    // ---- epilogue: O/l -> g_Oc split rows [hi|lo|hi]
    const int bq = bh >> 4;
    const int h  = bh & 15;
    float inv0 = 1.0f / lr0, inv1 = 1.0f / lr1;
#pragma unroll
    for (int e = 0; e < 2; e++) {
        int trow = t0 + wid * 16 + g + e * 8;
        float inv = e ? inv1 : inv0;
        size_t rowbase = (size_t)(bq * SEQ + trow) * K3 + h * DHEAD;
#pragma unroll
        for (int jd = 0; jd < 8; jd++) {
            int d = jd * 8 + tq * 2;
            float v0 = oacc[jd][e * 2 + 0] * inv;
            float v1 = oacc[jd][e * 2 + 1] * inv;
            __nv_bfloat16 h0 = __float2bfloat16(v0), h1 = __float2bfloat16(v1);
            __nv_bfloat16 l0 = __float2bfloat16(v0 - __bfloat162float(h0));
            __nv_bfloat16 l1 = __float2bfloat16(v1 - __bfloat162float(h1));
            __nv_bfloat162 hh = __halves2bfloat162(h0, h1);
            __nv_bfloat162 ll = __halves2bfloat162(l0, l1);
            *reinterpret_cast<__nv_bfloat162*>(g_Oc + rowbase + d)        = hh;
            *reinterpret_cast<__nv_bfloat162*>(g_Oc + rowbase + 1024 + d) = ll;
            *reinterpret_cast<__nv_bfloat162*>(g_Oc + rowbase + 2048 + d) = hh;
        }
    }
}

// ---------------------------------------------------------------------------
extern "C" void kernel_launch(void* const* d_in, const int* in_sizes, int n_in,
                              void* d_out, int out_size) {
    const float* q   = (const float*)d_in[0];
    const float* kv  = (const float*)d_in[1];
    const float* Wq  = (const float*)d_in[2];
    const float* Wkv = (const float*)d_in[3];
    const float* W0  = (const float*)d_in[4];
    float* out = (float*)d_out;
    (void)in_sizes; (void)n_in; (void)out_size;

    (void)cudaFuncSetAttribute(attn_mma, cudaFuncAttributeMaxDynamicSharedMemorySize, ATTN_SMEM);
    (void)cudaFuncSetAttribute(gemm_mma<0>, cudaFuncAttributeMaxDynamicSharedMemorySize, GEMM_SMEM);
    (void)cudaFuncSetAttribute(gemm_mma<1>, cudaFuncAttributeMaxDynamicSharedMemorySize, GEMM_SMEM);
    (void)cudaFuncSetAttribute(gemm_mma<2>, cudaFuncAttributeMaxDynamicSharedMemorySize, GEMM_SMEM);

    split3<0><<<(MROWS * 512 + 255) / 256, 256>>>(q,   MROWS * 512);
    split3<1><<<(MROWS * 512 + 255) / 256, 256>>>(kv,  MROWS * 512);
    split3<2><<<(1024 * 512 + 255) / 256, 256>>>(Wq,  1024 * 512);
    split3<3><<<(2048 * 512 + 255) / 256, 256>>>(Wkv, 2048 * 512);
    split3<4><<<(1024 * 512 + 255) / 256, 256>>>(W0,  1024 * 512);

    gemm_mma<0><<<dim3(EDIM / 128, MROWS / 128), 256, GEMM_SMEM>>>(nullptr);
    gemm_mma<1><<<dim3(2 * EDIM / 128, MROWS / 128), 256, GEMM_SMEM>>>(nullptr);
    attn_mma<<<dim3(SEQ / 128, BATCH * HEADS), 256, ATTN_SMEM>>>();
    gemm_mma<2><<<dim3(DMODEL / 128, MROWS / 128), 256, GEMM_SMEM>>>(out);
}

// round 8
// speedup vs baseline: 2.2838x; 1.0240x over previous
#include <cuda_runtime.h>
#include <cuda_bf16.h>
#include <cstdint>

// Problem constants
#define BATCH   4
#define SEQ     2048
#define DMODEL  1024
#define HEADS   16
#define DHEAD   64
#define EDIM    1024
#define MROWS   (BATCH * SEQ)     // 8192
#define K3      3072              // split-bf16 K' = 3*1024

// ---------------------------------------------------------------------------
// Scratch (device globals; no allocation allowed)
// ---------------------------------------------------------------------------
__device__ __align__(256) __nv_bfloat16 g_Qh[(size_t)BATCH * HEADS * SEQ * DHEAD];
__device__ __align__(256) __nv_bfloat16 g_Ql[(size_t)BATCH * HEADS * SEQ * DHEAD];
__device__ __align__(256) __nv_bfloat16 g_Kh[(size_t)BATCH * HEADS * SEQ * DHEAD];
__device__ __align__(256) __nv_bfloat16 g_Kl[(size_t)BATCH * HEADS * SEQ * DHEAD];
__device__ __align__(256) __nv_bfloat16 g_Vh[(size_t)BATCH * HEADS * SEQ * DHEAD];
__device__ __align__(256) __nv_bfloat16 g_Vl[(size_t)BATCH * HEADS * SEQ * DHEAD];
__device__ __align__(256) __nv_bfloat16 g_Aq [(size_t)MROWS * K3];
__device__ __align__(256) __nv_bfloat16 g_Akv[(size_t)MROWS * K3];
__device__ __align__(256) __nv_bfloat16 g_Oc [(size_t)MROWS * K3];
__device__ __align__(256) __nv_bfloat16 g_Wqc [(size_t)1024 * K3];
__device__ __align__(256) __nv_bfloat16 g_Wkvc[(size_t)2048 * K3];
__device__ __align__(256) __nv_bfloat16 g_W0c [(size_t)1024 * K3];

// ---------------------------------------------------------------------------
// Helpers
// ---------------------------------------------------------------------------
__device__ __forceinline__ uint32_t smem_u32(const void* p) {
    uint32_t a;
    asm("{ .reg .u64 t; cvta.to.shared.u64 t, %1; cvt.u32.u64 %0, t; }" : "=r"(a) : "l"(p));
    return a;
}
__device__ __forceinline__ void cp_async16(uint32_t smem_addr, const void* gptr) {
    asm volatile("cp.async.cg.shared.global [%0], [%1], 16;" :: "r"(smem_addr), "l"(gptr));
}
#define CP_COMMIT() asm volatile("cp.async.commit_group;" ::: "memory")
#define CP_WAIT(n)  asm volatile("cp.async.wait_group %0;" :: "n"(n) : "memory")

__device__ __forceinline__ void ldmatrix_x4(uint32_t& r0, uint32_t& r1, uint32_t& r2,
                                            uint32_t& r3, uint32_t addr) {
    asm volatile("ldmatrix.sync.aligned.m8n8.x4.shared.b16 {%0,%1,%2,%3}, [%4];"
                 : "=r"(r0), "=r"(r1), "=r"(r2), "=r"(r3) : "r"(addr));
}
__device__ __forceinline__ void ldmatrix_x4_trans(uint32_t& r0, uint32_t& r1, uint32_t& r2,
                                                  uint32_t& r3, uint32_t addr) {
    asm volatile("ldmatrix.sync.aligned.m8n8.x4.trans.shared.b16 {%0,%1,%2,%3}, [%4];"
                 : "=r"(r0), "=r"(r1), "=r"(r2), "=r"(r3) : "r"(addr));
}
__device__ __forceinline__ void mma_bf16(float* c,
                                         uint32_t a0, uint32_t a1, uint32_t a2, uint32_t a3,
                                         uint32_t b0, uint32_t b1) {
    asm volatile(
        "mma.sync.aligned.m16n8k16.row.col.f32.bf16.bf16.f32 "
        "{%0,%1,%2,%3}, {%4,%5,%6,%7}, {%8,%9}, {%0,%1,%2,%3};"
        : "+f"(c[0]), "+f"(c[1]), "+f"(c[2]), "+f"(c[3])
        : "r"(a0), "r"(a1), "r"(a2), "r"(a3), "r"(b0), "r"(b1));
}
__device__ __forceinline__ uint32_t pack_bf16x2(float x, float y) {
    __nv_bfloat162 t = __halves2bfloat162(__float2bfloat16(x), __float2bfloat16(y));
    return *reinterpret_cast<uint32_t*>(&t);
}

// ---------------------------------------------------------------------------
// split3: fp32 [R,1024] -> bf16 [R,3072]
// activations (0,1): [hi | lo | hi];  weights (2,3,4): [hi | hi | lo]
// ---------------------------------------------------------------------------
template <int WHICH>
__global__ void split3(const float* __restrict__ src, int total2) {
    __nv_bfloat16* dst = (WHICH == 0) ? g_Aq : (WHICH == 1) ? g_Akv :
                         (WHICH == 2) ? g_Wqc : (WHICH == 3) ? g_Wkvc : g_W0c;
    int idx = blockIdx.x * blockDim.x + threadIdx.x;
    if (idx >= total2) return;
    int r  = idx >> 9;
    int c2 = (idx & 511) << 1;
    float2 v = *reinterpret_cast<const float2*>(src + ((size_t)r << 10) + c2);
    __nv_bfloat16 h0 = __float2bfloat16(v.x), h1 = __float2bfloat16(v.y);
    __nv_bfloat16 l0 = __float2bfloat16(v.x - __bfloat162float(h0));
    __nv_bfloat16 l1 = __float2bfloat16(v.y - __bfloat162float(h1));
    size_t o = (size_t)r * K3;
    __nv_bfloat162 hh = __halves2bfloat162(h0, h1);
    __nv_bfloat162 ll = __halves2bfloat162(l0, l1);
    if (WHICH <= 1) {
        *reinterpret_cast<__nv_bfloat162*>(dst + o + c2)        = hh;
        *reinterpret_cast<__nv_bfloat162*>(dst + o + 1024 + c2) = ll;
        *reinterpret_cast<__nv_bfloat162*>(dst + o + 2048 + c2) = hh;
    } else {
        *reinterpret_cast<__nv_bfloat162*>(dst + o + c2)        = hh;
        *reinterpret_cast<__nv_bfloat162*>(dst + o + 1024 + c2) = hh;
        *reinterpret_cast<__nv_bfloat162*>(dst + o + 2048 + c2) = ll;
    }
}

// ---------------------------------------------------------------------------
// mma.sync bf16 TN GEMM, 128x128 tile, BK=64, 8 warps (2x4), warp 64x32.
// 3-stage ring, ONE barrier per chunk, loads issued at top of iteration.
// ---------------------------------------------------------------------------
#define NCH         (K3 / 64)            // 48
#define ROWB        144                  // 64 bf16 = 128B data + 16B pad
#define TILE_B      (128 * ROWB)         // 18432
#define STAGE_B     (2 * TILE_B)         // 36864
#define GEMM_SMEM   (3 * STAGE_B)        // 110592

template <int MODE>
__global__ __launch_bounds__(256) void gemm_mma(float* __restrict__ C) {
    extern __shared__ char smem[];
    const uint32_t sb = smem_u32(smem);
    const int tid = threadIdx.x, wid = tid >> 5, lane = tid & 31;
    const int wm = wid >> 2, wn = wid & 3;
    const int m0 = blockIdx.y * 128, n0 = blockIdx.x * 128;

    const __nv_bfloat16* Ag = (MODE == 0) ? g_Aq : (MODE == 1) ? g_Akv : g_Oc;
    const __nv_bfloat16* Bg = (MODE == 0) ? g_Wqc : (MODE == 1) ? g_Wkvc : g_W0c;
    Ag += (size_t)m0 * K3;
    Bg += (size_t)n0 * K3;

    float acc[4][4][4];
#pragma unroll
    for (int i = 0; i < 4; i++)
#pragma unroll
        for (int j = 0; j < 4; j++)
#pragma unroll
            for (int e = 0; e < 4; e++) acc[i][j][e] = 0.0f;

    auto load_stage = [&](int ch, int s) {
        uint32_t base = sb + s * STAGE_B;
#pragma unroll
        for (int t = 0; t < 8; t++) {
            int idx = tid + t * 256;            // 0..2047
            int op  = idx >> 10;                // 0=A,1=B
            int row = (idx >> 3) & 127;
            int ck  = idx & 7;
            const __nv_bfloat16* src = op ? Bg : Ag;
            cp_async16(base + op * TILE_B + row * ROWB + ck * 16,
                       src + (size_t)row * K3 + ch * 64 + ck * 8);
        }
        CP_COMMIT();
    };

    load_stage(0, 0);
    load_stage(1, 1);

    const uint32_t a_row = (uint32_t)(wm * 64 + (lane & 15));
    const uint32_t a_kb  = (uint32_t)(((lane >> 4) & 1) * 16);
    const uint32_t b_row = (uint32_t)(wn * 32 + (lane & 7) + ((lane >> 4) & 1) * 8);
    const uint32_t b_kb  = (uint32_t)(((lane >> 3) & 1) * 16);

    for (int ch = 0; ch < NCH; ch++) {
        if (ch + 1 < NCH) { CP_WAIT(1); } else { CP_WAIT(0); }
        __syncthreads();
        if (ch + 2 < NCH) load_stage(ch + 2, (ch + 2) % 3);

        uint32_t aBase = sb + (ch % 3) * STAGE_B;
        uint32_t bBase = aBase + TILE_B;
#pragma unroll
        for (int ks = 0; ks < 4; ks++) {
            uint32_t a[4][4], b[4][2];
#pragma unroll
            for (int i = 0; i < 4; i++) {
                uint32_t addr = aBase + (a_row + i * 16) * ROWB + ks * 32 + a_kb;
                ldmatrix_x4(a[i][0], a[i][1], a[i][2], a[i][3], addr);
            }
#pragma unroll
            for (int j2 = 0; j2 < 2; j2++) {
                uint32_t r0, r1, r2, r3;
                uint32_t addr = bBase + (b_row + j2 * 16) * ROWB + ks * 32 + b_kb;
                ldmatrix_x4(r0, r1, r2, r3, addr);
                b[j2 * 2][0] = r0; b[j2 * 2][1] = r1;
                b[j2 * 2 + 1][0] = r2; b[j2 * 2 + 1][1] = r3;
            }
#pragma unroll
            for (int i = 0; i < 4; i++)
#pragma unroll
                for (int j = 0; j < 4; j++)
                    mma_bf16(acc[i][j], a[i][0], a[i][1], a[i][2], a[i][3], b[j][0], b[j][1]);
        }
    }

    const int g = lane >> 2, tq = lane & 3;
#pragma unroll
    for (int i = 0; i < 4; i++) {
#pragma unroll
        for (int e = 0; e < 2; e++) {
            int m = m0 + wm * 64 + i * 16 + g + e * 8;
            int b = m >> 11;
            int t = m & 2047;
#pragma unroll
            for (int j = 0; j < 4; j++) {
#pragma unroll
                for (int x = 0; x < 2; x++) {
                    int n = n0 + wn * 32 + j * 8 + tq * 2 + x;
                    float v = acc[i][j][e * 2 + x];
                    if (MODE == 0) {
                        int d = n >> 4, h = n & 15;
                        size_t a5 = ((((size_t)b * HEADS + h) * SEQ + t) << 6) + d;
                        float vs = v * 0.125f;
                        __nv_bfloat16 hi = __float2bfloat16(vs);
                        g_Qh[a5] = hi;
                        g_Ql[a5] = __float2bfloat16(vs - __bfloat162float(hi));
                    } else if (MODE == 1) {
                        int h = n & 15, kk = (n >> 4) & 1, d = n >> 5;
                        size_t a5 = ((((size_t)b * HEADS + h) * SEQ + t) << 6) + d;
                        __nv_bfloat16 hi = __float2bfloat16(v);
                        __nv_bfloat16 lo = __float2bfloat16(v - __bfloat162float(hi));
                        if (kk) { g_Vh[a5] = hi; g_Vl[a5] = lo; }
                        else    { g_Kh[a5] = hi; g_Kl[a5] = lo; }
                    } else {
                        C[(size_t)m * 1024 + n] = v;
                    }
                }
            }
        }
    }
}

// ---------------------------------------------------------------------------
// Flash attention on mma.sync. CTA: 128 q-rows, 8 warps, key tiles of 64.
// 3-stage KV ring, ONE barrier per tile, loads issued at top of iteration.
// ---------------------------------------------------------------------------
#define AROWB    144
#define ATILE_B  (64 * AROWB)            // 9216
#define ASTAGE_B (4 * ATILE_B)           // 36864  (Kh|Kl|Vh|Vl)
#define ATTN_SMEM (3 * ASTAGE_B)         // 110592

__global__ __launch_bounds__(256) void attn_mma() {
    extern __shared__ char smem[];
    const uint32_t sb = smem_u32(smem);
    const int tid = threadIdx.x, wid = tid >> 5, lane = tid & 31;
    const int g = lane >> 2, tq = lane & 3;
    const int bh = blockIdx.y;
    const int t0 = blockIdx.x << 7;

    const size_t bhoff = (size_t)bh * SEQ * DHEAD;
    const __nv_bfloat16* Qh = g_Qh + bhoff + (size_t)t0 * DHEAD;
    const __nv_bfloat16* Ql = g_Ql + bhoff + (size_t)t0 * DHEAD;
    const __nv_bfloat16* Kh = g_Kh + bhoff;
    const __nv_bfloat16* Kl = g_Kl + bhoff;
    const __nv_bfloat16* Vh = g_Vh + bhoff;
    const __nv_bfloat16* Vl = g_Vl + bhoff;

    // ---- Stage Q in stage-0 smem and extract fragments
#pragma unroll
    for (int t = 0; t < 8; t++) {
        int idx = tid + t * 256;
        int mat = idx >> 10;
        int r   = (idx >> 3) & 127;
        int ck  = idx & 7;
        const __nv_bfloat16* src = mat ? Ql : Qh;
        cp_async16(sb + mat * (2 * ATILE_B) + r * AROWB + ck * 16,
                   src + (size_t)r * DHEAD + ck * 8);
    }
    CP_COMMIT();
    CP_WAIT(0);
    __syncthreads();

    uint32_t qh[4][4], ql[4][4];
    {
        uint32_t qrow = (uint32_t)(wid * 16 + (lane & 15));
        uint32_t kb   = (uint32_t)(((lane >> 4) & 1) * 16);
#pragma unroll
        for (int ks = 0; ks < 4; ks++) {
            uint32_t addr = sb + qrow * AROWB + ks * 32 + kb;
            ldmatrix_x4(qh[ks][0], qh[ks][1], qh[ks][2], qh[ks][3], addr);
            ldmatrix_x4(ql[ks][0], ql[ks][1], ql[ks][2], ql[ks][3],
                        addr + 2 * ATILE_B);
        }
    }
    __syncthreads();

    auto load_kv = [&](int jt, int s) {
        uint32_t base = sb + s * ASTAGE_B;
        const __nv_bfloat16* ptrs[4] = {Kh, Kl, Vh, Vl};
#pragma unroll
        for (int t = 0; t < 8; t++) {
            int idx = tid + t * 256;
            int mat = idx >> 9;
            int r   = (idx >> 3) & 63;
            int ck  = idx & 7;
            cp_async16(base + mat * ATILE_B + r * AROWB + ck * 16,
                       ptrs[mat] + (size_t)(jt * 64 + r) * DHEAD + ck * 8);
        }
        CP_COMMIT();
    };

    load_kv(0, 0);
    load_kv(1, 1);

    float oacc[8][4];
#pragma unroll
    for (int j = 0; j < 8; j++)
#pragma unroll
        for (int e = 0; e < 4; e++) oacc[j][e] = 0.0f;
    float mr0 = -1e30f, mr1 = -1e30f, lr0 = 0.0f, lr1 = 0.0f;

    const uint32_t kb_row = (uint32_t)((lane & 7) + ((lane >> 4) & 1) * 8);
    const uint32_t kb_kb  = (uint32_t)(((lane >> 3) & 1) * 16);
    const uint32_t v_row  = (uint32_t)((lane & 7) + ((lane >> 3) & 1) * 8);
    const uint32_t v_cb   = (uint32_t)(((lane >> 4) & 1) * 8 * 2);

    for (int jt = 0; jt < SEQ / 64; jt++) {
        if (jt + 1 < SEQ / 64) { CP_WAIT(1); } else { CP_WAIT(0); }
        __syncthreads();
        if (jt + 2 < SEQ / 64) load_kv(jt + 2, (jt + 2) % 3);
        uint32_t st = sb + (jt % 3) * ASTAGE_B;

        // ---- S = Qh*Kh + Ql*Kh + Qh*Kl
        float sacc[8][4];
#pragma unroll
        for (int j = 0; j < 8; j++)
#pragma unroll
            for (int e = 0; e < 4; e++) sacc[j][e] = 0.0f;
#pragma unroll
        for (int ks = 0; ks < 4; ks++) {
            uint32_t bt[8][2];
#pragma unroll
            for (int j2 = 0; j2 < 4; j2++) {
                uint32_t r0, r1, r2, r3;
                uint32_t addr = st + (kb_row + j2 * 16) * AROWB + ks * 32 + kb_kb;
                ldmatrix_x4(r0, r1, r2, r3, addr);
                bt[j2 * 2][0] = r0; bt[j2 * 2][1] = r1;
                bt[j2 * 2 + 1][0] = r2; bt[j2 * 2 + 1][1] = r3;
            }
#pragma unroll
            for (int j = 0; j < 8; j++)
                mma_bf16(sacc[j], qh[ks][0], qh[ks][1], qh[ks][2], qh[ks][3],
                         bt[j][0], bt[j][1]);
#pragma unroll
            for (int j = 0; j < 8; j++)
                mma_bf16(sacc[j], ql[ks][0], ql[ks][1], ql[ks][2], ql[ks][3],
                         bt[j][0], bt[j][1]);
#pragma unroll
            for (int j2 = 0; j2 < 4; j2++) {
                uint32_t r0, r1, r2, r3;
                uint32_t addr = st + ATILE_B + (kb_row + j2 * 16) * AROWB + ks * 32 + kb_kb;
                ldmatrix_x4(r0, r1, r2, r3, addr);
                bt[j2 * 2][0] = r0; bt[j2 * 2][1] = r1;
                bt[j2 * 2 + 1][0] = r2; bt[j2 * 2 + 1][1] = r3;
            }
#pragma unroll
            for (int j = 0; j < 8; j++)
                mma_bf16(sacc[j], qh[ks][0], qh[ks][1], qh[ks][2], qh[ks][3],
                         bt[j][0], bt[j][1]);
        }

        // ---- online softmax
        float mx0 = -1e30f, mx1 = -1e30f;
#pragma unroll
        for (int j = 0; j < 8; j++) {
            mx0 = fmaxf(mx0, fmaxf(sacc[j][0], sacc[j][1]));
            mx1 = fmaxf(mx1, fmaxf(sacc[j][2], sacc[j][3]));
        }
        mx0 = fmaxf(mx0, __shfl_xor_sync(0xffffffffu, mx0, 1));
        mx0 = fmaxf(mx0, __shfl_xor_sync(0xffffffffu, mx0, 2));
        mx1 = fmaxf(mx1, __shfl_xor_sync(0xffffffffu, mx1, 1));
        mx1 = fmaxf(mx1, __shfl_xor_sync(0xffffffffu, mx1, 2));
        float mn0 = fmaxf(mr0, mx0), mn1 = fmaxf(mr1, mx1);
        float al0 = __expf(mr0 - mn0), al1 = __expf(mr1 - mn1);
        mr0 = mn0; mr1 = mn1;
        float sum0 = 0.0f, sum1 = 0.0f;
#pragma unroll
        for (int j = 0; j < 8; j++) {
            sacc[j][0] = __expf(sacc[j][0] - mn0);
            sacc[j][1] = __expf(sacc[j][1] - mn0);
            sacc[j][2] = __expf(sacc[j][2] - mn1);
            sacc[j][3] = __expf(sacc[j][3] - mn1);
            sum0 += sacc[j][0] + sacc[j][1];
            sum1 += sacc[j][2] + sacc[j][3];
        }
        sum0 += __shfl_xor_sync(0xffffffffu, sum0, 1);
        sum0 += __shfl_xor_sync(0xffffffffu, sum0, 2);
        sum1 += __shfl_xor_sync(0xffffffffu, sum1, 1);
        sum1 += __shfl_xor_sync(0xffffffffu, sum1, 2);
        lr0 = lr0 * al0 + sum0;
        lr1 = lr1 * al1 + sum1;
#pragma unroll
        for (int j = 0; j < 8; j++) {
            oacc[j][0] *= al0; oacc[j][1] *= al0;
            oacc[j][2] *= al1; oacc[j][3] *= al1;
        }

        // ---- O += Ph*Vh + Pl*Vh + Ph*Vl
#pragma unroll
        for (int cs = 0; cs < 4; cs++) {
            int j0 = cs * 2, j1 = cs * 2 + 1;
            uint32_t ph[4], pl[4];
            {
                float p00 = sacc[j0][0], p01 = sacc[j0][1];
                float p02 = sacc[j0][2], p03 = sacc[j0][3];
                float p10 = sacc[j1][0], p11 = sacc[j1][1];
                float p12 = sacc[j1][2], p13 = sacc[j1][3];
                ph[0] = pack_bf16x2(p00, p01);
                ph[1] = pack_bf16x2(p02, p03);
                ph[2] = pack_bf16x2(p10, p11);
                ph[3] = pack_bf16x2(p12, p13);
                __nv_bfloat162 h;
                h = *reinterpret_cast<__nv_bfloat162*>(&ph[0]);
                pl[0] = pack_bf16x2(p00 - __bfloat162float(h.x), p01 - __bfloat162float(h.y));
                h = *reinterpret_cast<__nv_bfloat162*>(&ph[1]);
                pl[1] = pack_bf16x2(p02 - __bfloat162float(h.x), p03 - __bfloat162float(h.y));
                h = *reinterpret_cast<__nv_bfloat162*>(&ph[2]);
                pl[2] = pack_bf16x2(p10 - __bfloat162float(h.x), p11 - __bfloat162float(h.y));
                h = *reinterpret_cast<__nv_bfloat162*>(&ph[3]);
                pl[3] = pack_bf16x2(p12 - __bfloat162float(h.x), p13 - __bfloat162float(h.y));
            }
            uint32_t vt[8][2];
#pragma unroll
            for (int jd2 = 0; jd2 < 4; jd2++) {
                uint32_t r0, r1, r2, r3;
                uint32_t addr = st + 2 * ATILE_B + (cs * 16 + v_row) * AROWB
                              + jd2 * 32 + v_cb;
                ldmatrix_x4_trans(r0, r1, r2, r3, addr);
                vt[jd2 * 2][0] = r0; vt[jd2 * 2][1] = r1;
                vt[jd2 * 2 + 1][0] = r2; vt[jd2 * 2 + 1][1] = r3;
            }
#pragma unroll
            for (int jd = 0; jd < 8; jd++)
                mma_bf16(oacc[jd], ph[0], ph[1], ph[2], ph[3], vt[jd][0], vt[jd][1]);
#pragma unroll
            for (int jd = 0; jd < 8; jd++)
                mma_bf16(oacc[jd], pl[0], pl[1], pl[2], pl[3], vt[jd][0], vt[jd][1]);
#pragma unroll
            for (int jd2 = 0; jd2 < 4; jd2++) {
                uint32_t r0, r1, r2, r3;
                uint32_t addr = st + 3 * ATILE_B + (cs * 16 + v_row) * AROWB
                              + jd2 * 32 + v_cb;
                ldmatrix_x4_trans(r0, r1, r2, r3, addr);
                vt[jd2 * 2][0] = r0; vt[jd2 * 2][1] = r1;
                vt[jd2 * 2 + 1][0] = r2; vt[jd2 * 2 + 1][1] = r3;
            }
#pragma unroll
            for (int jd = 0; jd < 8; jd++)
                mma_bf16(oacc[jd], ph[0], ph[1], ph[2], ph[3], vt[jd][0], vt[jd][1]);
        }
    }

    // ---- epilogue
    const int bq = bh >> 4;
    const int h  = bh & 15;
    float inv0 = 1.0f / lr0, inv1 = 1.0f / lr1;
#pragma unroll
    for (int e = 0; e < 2; e++) {
        int trow = t0 + wid * 16 + g + e * 8;
        float inv = e ? inv1 : inv0;
        size_t rowbase = (size_t)(bq * SEQ + trow) * K3 + h * DHEAD;
#pragma unroll
        for (int jd = 0; jd < 8; jd++) {
            int d = jd * 8 + tq * 2;
            float v0 = oacc[jd][e * 2 + 0] * inv;
            float v1 = oacc[jd][e * 2 + 1] * inv;
            __nv_bfloat16 h0 = __float2bfloat16(v0), h1 = __float2bfloat16(v1);
            __nv_bfloat16 l0 = __float2bfloat16(v0 - __bfloat162float(h0));
            __nv_bfloat16 l1 = __float2bfloat16(v1 - __bfloat162float(h1));
            __nv_bfloat162 hh = __halves2bfloat162(h0, h1);
            __nv_bfloat162 ll = __halves2bfloat162(l0, l1);
            *reinterpret_cast<__nv_bfloat162*>(g_Oc + rowbase + d)        = hh;
            *reinterpret_cast<__nv_bfloat162*>(g_Oc + rowbase + 1024 + d) = ll;
            *reinterpret_cast<__nv_bfloat162*>(g_Oc + rowbase + 2048 + d) = hh;
        }
    }
}

// ---------------------------------------------------------------------------
extern "C" void kernel_launch(void* const* d_in, const int* in_sizes, int n_in,
                              void* d_out, int out_size) {
    const float* q   = (const float*)d_in[0];
    const float* kv  = (const float*)d_in[1];
    const float* Wq  = (const float*)d_in[2];
    const float* Wkv = (const float*)d_in[3];
    const float* W0  = (const float*)d_in[4];
    float* out = (float*)d_out;
    (void)in_sizes; (void)n_in; (void)out_size;

    (void)cudaFuncSetAttribute(attn_mma, cudaFuncAttributeMaxDynamicSharedMemorySize, ATTN_SMEM);
    (void)cudaFuncSetAttribute(gemm_mma<0>, cudaFuncAttributeMaxDynamicSharedMemorySize, GEMM_SMEM);
    (void)cudaFuncSetAttribute(gemm_mma<1>, cudaFuncAttributeMaxDynamicSharedMemorySize, GEMM_SMEM);
    (void)cudaFuncSetAttribute(gemm_mma<2>, cudaFuncAttributeMaxDynamicSharedMemorySize, GEMM_SMEM);

    split3<0><<<(MROWS * 512 + 255) / 256, 256>>>(q,   MROWS * 512);
    split3<1><<<(MROWS * 512 + 255) / 256, 256>>>(kv,  MROWS * 512);
    split3<2><<<(1024 * 512 + 255) / 256, 256>>>(Wq,  1024 * 512);
    split3<3><<<(2048 * 512 + 255) / 256, 256>>>(Wkv, 2048 * 512);
    split3<4><<<(1024 * 512 + 255) / 256, 256>>>(W0,  1024 * 512);

    gemm_mma<0><<<dim3(EDIM / 128, MROWS / 128), 256, GEMM_SMEM>>>(nullptr);
    gemm_mma<1><<<dim3(2 * EDIM / 128, MROWS / 128), 256, GEMM_SMEM>>>(nullptr);
    attn_mma<<<dim3(SEQ / 128, BATCH * HEADS), 256, ATTN_SMEM>>>();
    gemm_mma<2><<<dim3(DMODEL / 128, MROWS / 128), 256, GEMM_SMEM>>>(out);
}